// round 15
// baseline (speedup 1.0000x reference)
#include <cuda_runtime.h>
#include <cuda_fp16.h>
#include <math.h>
#include <stdint.h>

#define BATCH   8
#define IN_CH   8
#define IMG     224
#define PATCHSZ 16
#define HGRID   14
#define LSEQ    1568            // 14*14*8
#define MROWS   12544           // BATCH*LSEQ = 98*128
#define DM      768
#define DI      1536
#define DS      16
#define DR      48
#define NC      1000
#define DEPTH   4
#define EPS_LN  1e-5f

// ---------------- device scratch ----------------
__device__ float g_res  [(size_t)MROWS * DM];
__device__ float g_hid  [(size_t)MROWS * DM];
__device__ float g_hn   [(size_t)MROWS * DM];
__device__ float g_xz   [(size_t)MROWS * 2 * DI];
__device__ float g_xc   [(size_t)MROWS * DI];
__device__ float g_dbc  [(size_t)MROWS * 80];
__device__ float g_dt   [(size_t)MROWS * DI];
__device__ float g_y    [(size_t)MROWS * DI];
__device__ float g_pool [BATCH * DM];

// fp16 buffers: weights single-rounded, activations hi/lo split
#define OFF_PW   0
#define OFF_IPW  196608
#define OFF_XPW  9633792
#define OFF_DTW  10420224
#define OFF_OPW  10813440
#define WTOT     15532032
#define PW_LEN   196608
#define XPW_LEN  786432
#define DTW_LEN  393216
#define REST_LEN 6094848   // PW + XPW + DTW + OPW
__device__ __half g_wh [WTOT];
__device__ __half g_ah [(size_t)MROWS * DI];
__device__ __half g_al [(size_t)MROWS * DI];
__device__ __half g_ph [(size_t)MROWS * 256];
__device__ __half g_pl [(size_t)MROWS * 256];
__device__ __half g_dbch[(size_t)MROWS * 64];   // cols 48..63 stay zero
__device__ __half g_dbcl[(size_t)MROWS * 64];

// ---------------- helpers ----------------
__device__ __forceinline__ float warp_sum(float v) {
#pragma unroll
    for (int o = 16; o; o >>= 1) v += __shfl_xor_sync(0xffffffffu, v, o);
    return v;
}
__device__ __forceinline__ float blk_sum(float v, float* sh) {
    int lane = threadIdx.x & 31, w = threadIdx.x >> 5;
    v = warp_sum(v);
    __syncthreads();
    if (lane == 0) sh[w] = v;
    __syncthreads();
    float t = (lane < 8) ? sh[lane] : 0.0f;
#pragma unroll
    for (int o = 4; o; o >>= 1) t += __shfl_xor_sync(0xffffffffu, t, o);
    return __shfl_sync(0xffffffffu, t, 0);
}
__device__ __forceinline__ uint32_t smem_u32(const void* p) {
    uint32_t a;
    asm("{ .reg .u64 t; cvta.to.shared.u64 t, %1; cvt.u32.u64 %0, t; }" : "=r"(a) : "l"(p));
    return a;
}
__device__ __forceinline__ void ldmx4(uint32_t addr, uint32_t& r0, uint32_t& r1,
                                      uint32_t& r2, uint32_t& r3) {
    asm volatile("ldmatrix.sync.aligned.m8n8.x4.shared.b16 {%0,%1,%2,%3}, [%4];"
                 : "=r"(r0), "=r"(r1), "=r"(r2), "=r"(r3) : "r"(addr));
}
__device__ __forceinline__ void mma16816(float* c, const uint32_t* a, uint32_t b0, uint32_t b1) {
    asm volatile(
        "mma.sync.aligned.m16n8k16.row.col.f32.f16.f16.f32 "
        "{%0,%1,%2,%3}, {%4,%5,%6,%7}, {%8,%9}, {%0,%1,%2,%3};"
        : "+f"(c[0]), "+f"(c[1]), "+f"(c[2]), "+f"(c[3])
        : "r"(a[0]), "r"(a[1]), "r"(a[2]), "r"(a[3]), "r"(b0), "r"(b1));
}
__device__ __forceinline__ void split_fp16(float v, __half& h, __half& l) {
    h = __float2half_rn(v);
    l = __float2half_rn(v - __half2float(h));
}

// ================= fp16-split HMMA GEMM (2-product, BK=64) =================
// CTA tile 128x128, BK=64, 512 threads (16 warps: 4m x 4n, warp tile 32x32).
// Reg-buffered gmem double-buffer, 1 sync per 64-wide chunk. K mult of 64.
// C[M,N] = (Ah+Al)[M,K] * Bh[N,K]^T, fp32 accum.
// mode: 0 plain, 1 +pb/ce, 2 +split to ehi/elo (n<48), 3 softplus(v + dtb[n])
#define TSTRIDE 72                 // halfs per smem row (64 + 8 pad)
#define TILE_B  18432              // 128*72*2 bytes
#define STAGE_B (3 * TILE_B)       // 55296 (Ah, Al, Bh)
#define GEMM_SMEM (2 * STAGE_B)    // 110592

__global__ void __launch_bounds__(512)
k_gemm_fp16(const __half* __restrict__ Ah, const __half* __restrict__ Al, int lda,
            const __half* __restrict__ Bh, int ldb,
            float* __restrict__ C, int ldc, int Ndim, int K,
            int mode, const float* __restrict__ pb, const float* __restrict__ ce,
            __half* __restrict__ ehi, __half* __restrict__ elo,
            const float* __restrict__ dtb) {
    extern __shared__ __align__(16) char sm[];
    uint32_t sbase = smem_u32(sm);

    int tid  = threadIdx.x;
    int wid  = tid >> 5;
    int lane = tid & 31;
    int bm = blockIdx.y * 128;
    int bn = blockIdx.x * 128;
    int warp_m = wid & 3;        // 0..3, 32 rows each
    int warp_n = wid >> 2;       // 0..3, 32 cols each

    // loader: each tile = 1024 uint4; thread handles ids tid, tid+512
    // row = id>>3 (0..127), colq = (id&7)*8 halfs
    int lr0 = tid >> 3;            // 0..63
    int lq0 = (tid & 7) * 8;

    float acc[2][4][4];
#pragma unroll
    for (int i = 0; i < 2; i++)
#pragma unroll
        for (int j = 0; j < 4; j++)
#pragma unroll
            for (int q = 0; q < 4; q++) acc[i][j][q] = 0.0f;

    int arow = warp_m * 32 + (lane & 15);
    int brow = warp_n * 32 + (lane & 15);
    int koff0 = ((lane >> 4) * 8) * 2;     // bytes

    int nch = K >> 6;
    uint4 lvA[2], lvL[2], lvB[2];

    // prologue: chunk 0 -> regs -> stage 0
#pragma unroll
    for (int i = 0; i < 2; i++) {
        int r = lr0 + i * 64;
        lvA[i] = *(const uint4*)(Ah + (size_t)(bm + r) * lda + lq0);
        lvL[i] = *(const uint4*)(Al + (size_t)(bm + r) * lda + lq0);
        lvB[i] = *(const uint4*)(Bh + (size_t)(bn + r) * ldb + lq0);
    }
    {
#pragma unroll
        for (int i = 0; i < 2; i++) {
            int r = lr0 + i * 64;
            uint32_t ro = (uint32_t)(r * TSTRIDE + lq0) * 2;
            *(uint4*)(sm + ro) = lvA[i];
            *(uint4*)(sm + TILE_B + ro) = lvL[i];
            *(uint4*)(sm + 2 * TILE_B + ro) = lvB[i];
        }
    }
    __syncthreads();

    for (int c = 0; c < nch; c++) {
        bool more = (c + 1 < nch);
        if (more) {
            int k0 = (c + 1) << 6;
#pragma unroll
            for (int i = 0; i < 2; i++) {
                int r = lr0 + i * 64;
                lvA[i] = *(const uint4*)(Ah + (size_t)(bm + r) * lda + k0 + lq0);
                lvL[i] = *(const uint4*)(Al + (size_t)(bm + r) * lda + k0 + lq0);
                lvB[i] = *(const uint4*)(Bh + (size_t)(bn + r) * ldb + k0 + lq0);
            }
        }

        uint32_t stb = sbase + (c & 1) * STAGE_B;
#pragma unroll
        for (int ks = 0; ks < 4; ks++) {
            int kb = ks * 32 + koff0;
            uint32_t bh[2][4];
#pragma unroll
            for (int ng = 0; ng < 2; ng++) {
                uint32_t ob = stb + 2 * TILE_B + (uint32_t)((brow + ng * 16) * TSTRIDE) * 2 + kb;
                ldmx4(ob, bh[ng][0], bh[ng][1], bh[ng][2], bh[ng][3]);
            }
#pragma unroll
            for (int mt = 0; mt < 2; mt++) {
                uint32_t ah[4], al[4];
                uint32_t oa = stb + (uint32_t)((arow + mt * 16) * TSTRIDE) * 2 + kb;
                ldmx4(oa, ah[0], ah[1], ah[2], ah[3]);
                ldmx4(oa + TILE_B, al[0], al[1], al[2], al[3]);
#pragma unroll
                for (int nt = 0; nt < 4; nt++) {
                    int ng = nt >> 1, sel = nt & 1;
                    mma16816(acc[mt][nt], ah, bh[ng][sel], bh[ng][sel + 2]);
                    mma16816(acc[mt][nt], al, bh[ng][sel], bh[ng][sel + 2]);
                }
            }
        }

        if (more) {
            uint32_t d0 = ((c + 1) & 1) * STAGE_B;
#pragma unroll
            for (int i = 0; i < 2; i++) {
                int r = lr0 + i * 64;
                uint32_t ro = (uint32_t)(r * TSTRIDE + lq0) * 2;
                *(uint4*)(sm + d0 + ro) = lvA[i];
                *(uint4*)(sm + d0 + TILE_B + ro) = lvL[i];
                *(uint4*)(sm + d0 + 2 * TILE_B + ro) = lvB[i];
            }
        }
        __syncthreads();
    }

    // ---------- epilogue ----------
    int rg = lane >> 2;
    int cg = (lane & 3) * 2;
#pragma unroll
    for (int mt = 0; mt < 2; mt++) {
        int m = bm + warp_m * 32 + mt * 16 + rg;
#pragma unroll
        for (int nt = 0; nt < 4; nt++) {
            int n = bn + warp_n * 32 + nt * 8 + cg;
#pragma unroll
            for (int half = 0; half < 2; half++) {
                int mm = m + half * 8;
                float v0 = acc[mt][nt][half * 2];
                float v1 = acc[mt][nt][half * 2 + 1];
                if (mode == 1) {
                    int cc = (mm % LSEQ) & 7;
                    v0 += pb[n]     + ce[cc * DM + n];
                    v1 += pb[n + 1] + ce[cc * DM + n + 1];
                } else if (mode == 3) {
                    float a0 = v0 + dtb[n];
                    float a1 = v1 + dtb[n + 1];
                    v0 = (a0 > 20.0f) ? a0 : log1pf(expf(a0));
                    v1 = (a1 > 20.0f) ? a1 : log1pf(expf(a1));
                }
                if (n < Ndim)
                    *(float2*)(C + (size_t)mm * ldc + n) = make_float2(v0, v1);
                if (mode == 2 && n < 48) {
                    __half h0, l0, h1, l1;
                    split_fp16(v0, h0, l0);
                    split_fp16(v1, h1, l1);
                    size_t eo = (size_t)mm * 64 + n;
                    ehi[eo] = h0; ehi[eo + 1] = h1;
                    elo[eo] = l0; elo[eo + 1] = l1;
                }
            }
        }
    }
}

// ---------------- weight convert: big ipw -> fp16 ----------------
__global__ void k_splitw(const float* __restrict__ src, __half* __restrict__ hi, size_t n) {
    size_t idx = (size_t)blockIdx.x * 256 + threadIdx.x;
    if (idx >= n) return;
    hi[idx] = __float2half_rn(src[idx]);
}

// ---------------- weight convert: pw + xpw(pad rows) + dtw(pad cols) + opw ----------------
__global__ void k_splitw_rest(const float* __restrict__ pw, const float* __restrict__ xpw,
                              const float* __restrict__ dtw, const float* __restrict__ opw,
                              __half* __restrict__ hi) {
    size_t idx = (size_t)blockIdx.x * 256 + threadIdx.x;
    if (idx >= (size_t)REST_LEN) return;
    float v; size_t out;
    if (idx < PW_LEN) {
        v = pw[idx];
        out = OFF_PW + idx;
    } else if (idx < (size_t)PW_LEN + XPW_LEN) {
        size_t i2 = idx - PW_LEN;
        int lay = (int)(i2 / 196608);
        int w   = (int)(i2 % 196608);
        int r = w / 1536, cc = w % 1536;
        v = (r < 80) ? xpw[(size_t)lay * 122880 + (size_t)r * 1536 + cc] : 0.0f;
        out = OFF_XPW + i2;
    } else if (idx < (size_t)PW_LEN + XPW_LEN + DTW_LEN) {
        size_t i3 = idx - PW_LEN - XPW_LEN;
        int lay = (int)(i3 / 98304);
        int w   = (int)(i3 % 98304);
        int r = w >> 6, cc = w & 63;
        v = (cc < 48) ? dtw[(size_t)lay * 73728 + (size_t)r * 48 + cc] : 0.0f;
        out = OFF_DTW + i3;
    } else {
        size_t i4 = idx - PW_LEN - XPW_LEN - DTW_LEN;
        v = opw[i4];
        out = OFF_OPW + i4;
    }
    hi[out] = __float2half_rn(v);
}

// ---------------- im2col -> fp16 hi/lo ----------------
__global__ void k_im2col(const float* __restrict__ x, __half* __restrict__ hi,
                         __half* __restrict__ lo) {
    int row = blockIdx.x;
    int k   = threadIdx.x;
    int l  = row % LSEQ;
    int b  = row / LSEQ;
    int c  = l & 7;
    int hw = l >> 3;
    int wg = hw % HGRID;
    int hg = hw / HGRID;
    int p  = k >> 4;
    int q  = k & 15;
    float v = x[(((size_t)(b * IN_CH + c) * IMG) + (hg * PATCHSZ + p)) * IMG + (wg * PATCHSZ + q)];
    __half h, lw;
    split_fp16(v, h, lw);
    hi[(size_t)row * 256 + k] = h;
    lo[(size_t)row * 256 + k] = lw;
}

// ---------------- residual + LayerNorm (768) -> fp16 hi/lo or fp32 ----------------
__global__ void k_resid_ln(const float* __restrict__ hid, float* __restrict__ res,
                           float* __restrict__ hn,
                           __half* __restrict__ ohi, __half* __restrict__ olo,
                           const float* __restrict__ w, const float* __restrict__ b,
                           int first, int tofp16) {
    __shared__ float sh[8];
    int row = blockIdx.x;
    float v[3];
#pragma unroll
    for (int j = 0; j < 3; j++) {
        int c = threadIdx.x + j * 256;
        size_t idx = (size_t)row * DM + c;
        float r = first ? hid[idx] : (res[idx] + hid[idx]);
        res[idx] = r;
        v[j] = r;
    }
    float mean = blk_sum(v[0] + v[1] + v[2], sh) * (1.0f / DM);
    float sq = 0.f;
#pragma unroll
    for (int j = 0; j < 3; j++) { v[j] -= mean; sq += v[j] * v[j]; }
    float var = blk_sum(sq, sh) * (1.0f / DM);
    float iv = rsqrtf(var + EPS_LN);
#pragma unroll
    for (int j = 0; j < 3; j++) {
        int c = threadIdx.x + j * 256;
        size_t idx = (size_t)row * DM + c;
        float o = v[j] * iv * w[c] + b[c];
        if (tofp16) {
            __half h, l;
            split_fp16(o, h, l);
            ohi[idx] = h; olo[idx] = l;
        } else {
            hn[idx] = o;
        }
    }
}

// ---------------- depthwise conv(4) + SiLU -> fp32 + fp16 hi/lo ----------------
__global__ void k_conv_silu(const float* __restrict__ xz, const float* __restrict__ cw,
                            const float* __restrict__ cb, float* __restrict__ xc,
                            __half* __restrict__ ohi, __half* __restrict__ olo) {
    size_t idx = (size_t)blockIdx.x * 256 + threadIdx.x;
    if (idx >= (size_t)MROWS * DI) return;
    int e   = (int)(idx % DI);
    int row = (int)(idx / DI);
    int l   = row % LSEQ;
    float acc = cb[e];
    const float* cwp = cw + e * 4;
    size_t base = (size_t)row * (2 * DI) + e;
#pragma unroll
    for (int k = 0; k < 4; k++) {
        int ls = l - 3 + k;
        if (ls >= 0) acc += xz[base + (size_t)(k - 3) * (2 * DI)] * cwp[k];
    }
    float o = acc / (1.0f + expf(-acc));
    xc[idx] = o;
    __half h, lo_;
    split_fp16(o, h, lo_);
    ohi[idx] = h; olo[idx] = lo_;
}

// ---------------- selective scan, SMEM-tiled ----------------
#define SCH 64
#define STT 32
__global__ void __launch_bounds__(256)
k_scan(const float* __restrict__ dt, const float* __restrict__ xc,
       const float* __restrict__ dbc, const float* __restrict__ Alog,
       float* __restrict__ y) {
    __shared__ float sdt[STT][SCH];
    __shared__ float sxc[STT][SCH];
    __shared__ float sB[STT][16];
    __shared__ float sC[STT][16];

    int b  = blockIdx.y;
    int d0 = blockIdx.x * SCH;
    int tid = threadIdx.x;
    int ng  = tid & 3;
    int chl = tid >> 2;          // 0..63
    int d   = d0 + chl;

    float A0 = -expf(Alog[d * DS + ng * 4 + 0]);
    float A1 = -expf(Alog[d * DS + ng * 4 + 1]);
    float A2 = -expf(Alog[d * DS + ng * 4 + 2]);
    float A3 = -expf(Alog[d * DS + ng * 4 + 3]);

    float h0 = 0.f, h1 = 0.f, h2 = 0.f, h3 = 0.f;
    int rowbase = b * LSEQ;

    for (int t0 = 0; t0 < LSEQ; t0 += STT) {
        __syncthreads();
#pragma unroll
        for (int i = 0; i < 8; i++) {
            int id = tid + i * 256;          // 0..2047
            int tt = id >> 6, cc = id & 63;
            size_t g = (size_t)(rowbase + t0 + tt) * DI + d0 + cc;
            sdt[tt][cc] = dt[g];
            sxc[tt][cc] = xc[g];
        }
#pragma unroll
        for (int i = 0; i < 2; i++) {
            int id = tid + i * 256;          // 0..511
            int tt = id >> 4, nn = id & 15;
            const float* base = dbc + (size_t)(rowbase + t0 + tt) * 80;
            sB[tt][nn] = base[48 + nn];
            sC[tt][nn] = base[64 + nn];
        }
        __syncthreads();

#pragma unroll 4
        for (int tt = 0; tt < STT; tt++) {
            float dtv = sdt[tt][chl];
            float u = dtv * sxc[tt][chl];
            h0 = __expf(dtv * A0) * h0 + u * sB[tt][ng * 4 + 0];
            h1 = __expf(dtv * A1) * h1 + u * sB[tt][ng * 4 + 1];
            h2 = __expf(dtv * A2) * h2 + u * sB[tt][ng * 4 + 2];
            h3 = __expf(dtv * A3) * h3 + u * sB[tt][ng * 4 + 3];
            float p = h0 * sC[tt][ng * 4 + 0] + h1 * sC[tt][ng * 4 + 1]
                    + h2 * sC[tt][ng * 4 + 2] + h3 * sC[tt][ng * 4 + 3];
            p += __shfl_xor_sync(0xffffffffu, p, 1);
            p += __shfl_xor_sync(0xffffffffu, p, 2);
            if (ng == 0) y[(size_t)(rowbase + t0 + tt) * DI + d] = p;
        }
    }
}

// ---------------- y = LN(y + D*x) * silu(z) -> fp16 hi/lo ----------------
__global__ void k_ypost(const float* __restrict__ y, const float* __restrict__ xc,
                        const float* __restrict__ xz, const float* __restrict__ Dp,
                        const float* __restrict__ snw, const float* __restrict__ snb,
                        __half* __restrict__ ohi, __half* __restrict__ olo) {
    __shared__ float sh[8];
    int row = blockIdx.x;
    float v[6];
#pragma unroll
    for (int j = 0; j < 6; j++) {
        int c = threadIdx.x + j * 256;
        size_t idx = (size_t)row * DI + c;
        v[j] = y[idx] + Dp[c] * xc[idx];
    }
    float s = 0.f;
#pragma unroll
    for (int j = 0; j < 6; j++) s += v[j];
    float mean = blk_sum(s, sh) * (1.0f / DI);
    float sq = 0.f;
#pragma unroll
    for (int j = 0; j < 6; j++) { v[j] -= mean; sq += v[j] * v[j]; }
    float var = blk_sum(sq, sh) * (1.0f / DI);
    float iv = rsqrtf(var + EPS_LN);
#pragma unroll
    for (int j = 0; j < 6; j++) {
        int c = threadIdx.x + j * 256;
        float nv = v[j] * iv * snw[c] + snb[c];
        float z = xz[(size_t)row * (2 * DI) + DI + c];
        float o = nv * (z / (1.0f + expf(-z)));
        __half h, l;
        split_fp16(o, h, l);
        size_t idx = (size_t)row * DI + c;
        ohi[idx] = h; olo[idx] = l;
    }
}

// ---------------- mean-pool partial sums ----------------
__global__ void k_pool(const float* __restrict__ hn, float* __restrict__ pool) {
    int b = blockIdx.x;
    int chunk = blockIdx.y;
#pragma unroll
    for (int j = 0; j < 3; j++) {
        int d = threadIdx.x + j * 256;
        float s = 0.f;
        int l0 = chunk * 112;
        for (int l = l0; l < l0 + 112; l++)
            s += hn[((size_t)(b * LSEQ + l)) * DM + d];
        atomicAdd(&pool[b * DM + d], s);
    }
}

// ---------------- head ----------------
__global__ void k_head(const float* __restrict__ pool, const float* __restrict__ hw,
                       const float* __restrict__ hb, float* __restrict__ out) {
    int cls = blockIdx.x;
    int b   = threadIdx.x >> 5;
    int lane = threadIdx.x & 31;
    float s = 0.f;
    for (int d = lane; d < DM; d += 32)
        s += pool[b * DM + d] * hw[(size_t)cls * DM + d];
    s = warp_sum(s);
    if (lane == 0)
        out[b * NC + cls] = s * (1.0f / (float)LSEQ) + hb[cls];
}

// ---------------- launch ----------------
extern "C" void kernel_launch(void* const* d_in, const int* in_sizes, int n_in,
                              void* d_out, int out_size) {
    const float* x      = (const float*)d_in[0];
    const float* pw     = (const float*)d_in[1];
    const float* pb     = (const float*)d_in[2];
    const float* ce     = (const float*)d_in[3];
    const float* nw     = (const float*)d_in[4];
    const float* nb     = (const float*)d_in[5];
    const float* ipw    = (const float*)d_in[6];
    const float* cw     = (const float*)d_in[7];
    const float* cb     = (const float*)d_in[8];
    const float* xpw    = (const float*)d_in[9];
    const float* dtw    = (const float*)d_in[10];
    const float* dtb    = (const float*)d_in[11];
    const float* alog   = (const float*)d_in[12];
    const float* Dp     = (const float*)d_in[13];
    const float* snw    = (const float*)d_in[14];
    const float* snb    = (const float*)d_in[15];
    const float* opw    = (const float*)d_in[16];
    const float* nfw    = (const float*)d_in[17];
    const float* nfb    = (const float*)d_in[18];
    const float* hw     = (const float*)d_in[19];
    const float* hb     = (const float*)d_in[20];
    float* out = (float*)d_out;

    float *res, *hid, *hn, *xz, *xc, *dbc, *dtbuf, *ybuf, *pool;
    __half *wh, *ah, *al, *ph, *pl, *dbch, *dbcl;
    cudaGetSymbolAddress((void**)&res,   g_res);
    cudaGetSymbolAddress((void**)&hid,   g_hid);
    cudaGetSymbolAddress((void**)&hn,    g_hn);
    cudaGetSymbolAddress((void**)&xz,    g_xz);
    cudaGetSymbolAddress((void**)&xc,    g_xc);
    cudaGetSymbolAddress((void**)&dbc,   g_dbc);
    cudaGetSymbolAddress((void**)&dtbuf, g_dt);
    cudaGetSymbolAddress((void**)&ybuf,  g_y);
    cudaGetSymbolAddress((void**)&pool,  g_pool);
    cudaGetSymbolAddress((void**)&wh,    g_wh);
    cudaGetSymbolAddress((void**)&ah,    g_ah);
    cudaGetSymbolAddress((void**)&al,    g_al);
    cudaGetSymbolAddress((void**)&ph,    g_ph);
    cudaGetSymbolAddress((void**)&pl,    g_pl);
    cudaGetSymbolAddress((void**)&dbch,  g_dbch);
    cudaGetSymbolAddress((void**)&dbcl,  g_dbcl);

    cudaFuncSetAttribute(k_gemm_fp16, cudaFuncAttributeMaxDynamicSharedMemorySize, GEMM_SMEM);

    const int ew_di = (int)(((size_t)MROWS * DI + 255) / 256);
    const int MB = MROWS / 128;   // 98

    // launch 1: big ipw convert
    k_splitw<<<(int)(((size_t)12288 * 768 + 255) / 256), 256>>>(
        ipw, wh + OFF_IPW, (size_t)12288 * 768);
    // launch 2: all other weight converts
    k_splitw_rest<<<(REST_LEN + 255) / 256, 256>>>(pw, xpw, dtw, opw, wh);
    // launch 3: im2col
    k_im2col<<<MROWS, 256>>>(x, ph, pl);
    // launch 4: patch gemm (bias + channel-embed fused, mode 1)
    k_gemm_fp16<<<dim3(6, MB), 512, GEMM_SMEM>>>(ph, pl, 256,
        wh + OFF_PW, 256, hid, DM, DM, 256, 1, pb, ce, nullptr, nullptr, nullptr);

    for (int i = 0; i < DEPTH; i++) {
        // launch 5 (i=0): resid_ln; launch 6 (i=0): in_proj gemm  <- profiled by -s 5 -c 1
        k_resid_ln<<<MROWS, 256>>>(hid, res, nullptr, ah, al,
                                   nw + i * DM, nb + i * DM, i == 0 ? 1 : 0, 1);
        k_gemm_fp16<<<dim3(24, MB), 512, GEMM_SMEM>>>(ah, al, DM,
            wh + OFF_IPW + (size_t)i * 3072 * 768, DM,
            xz, 3072, 3072, DM, 0, nullptr, nullptr, nullptr, nullptr, nullptr);
        k_conv_silu<<<ew_di, 256>>>(xz, cw + (size_t)i * DI * 4, cb + i * DI, xc, ah, al);
        k_gemm_fp16<<<dim3(1, MB), 512, GEMM_SMEM>>>(ah, al, DI,
            wh + OFF_XPW + (size_t)i * 128 * 1536, DI,
            dbc, 80, 80, DI, 2, nullptr, nullptr, dbch, dbcl, nullptr);
        // dt gemm with fused softplus+bias (mode 3)
        k_gemm_fp16<<<dim3(12, MB), 512, GEMM_SMEM>>>(dbch, dbcl, 64,
            wh + OFF_DTW + (size_t)i * 1536 * 64, 64,
            dtbuf, DI, DI, 64, 3, nullptr, nullptr, nullptr, nullptr, dtb + i * DI);
        k_scan<<<dim3(DI / SCH, BATCH), 256>>>(dtbuf, xc, dbc,
                                               alog + (size_t)i * DI * DS, ybuf);
        k_ypost<<<MROWS, 256>>>(ybuf, xc, xz, Dp + i * DI, snw + i * DI, snb + i * DI, ah, al);
        k_gemm_fp16<<<dim3(6, MB), 512, GEMM_SMEM>>>(ah, al, DI,
            wh + OFF_OPW + (size_t)i * 768 * 1536, DI,
            hid, DM, DM, DI, 0, nullptr, nullptr, nullptr, nullptr, nullptr);
    }

    // final residual + LN + pool + head
    k_resid_ln<<<MROWS, 256>>>(hid, res, hn, nullptr, nullptr, nfw, nfb, 0, 0);
    cudaMemsetAsync(pool, 0, BATCH * DM * sizeof(float));
    k_pool<<<dim3(BATCH, 14), 256>>>(hn, pool);
    k_head<<<NC, 256>>>(pool, hw, hb, out);
}

// round 16
// speedup vs baseline: 1.0934x; 1.0934x over previous
#include <cuda_runtime.h>
#include <cuda_fp16.h>
#include <math.h>
#include <stdint.h>

#define BATCH   8
#define IN_CH   8
#define IMG     224
#define PATCHSZ 16
#define HGRID   14
#define LSEQ    1568            // 14*14*8
#define MROWS   12544           // BATCH*LSEQ = 98*128
#define DM      768
#define DI      1536
#define DS      16
#define DR      48
#define NC      1000
#define DEPTH   4
#define EPS_LN  1e-5f

// ---------------- device scratch ----------------
__device__ float g_res  [(size_t)MROWS * DM];
__device__ float g_hid  [(size_t)MROWS * DM];
__device__ float g_hn   [(size_t)MROWS * DM];
__device__ float g_xz   [(size_t)MROWS * 2 * DI];
__device__ float g_xc   [(size_t)MROWS * DI];
__device__ float g_dbc  [(size_t)MROWS * 80];
__device__ float g_dt   [(size_t)MROWS * DI];
__device__ float g_y    [(size_t)MROWS * DI];
__device__ float g_pool [BATCH * DM];

// fp16 buffers: weights single-rounded, activations hi/lo split
#define OFF_PW   0
#define OFF_IPW  196608
#define OFF_XPW  9633792
#define OFF_DTW  10420224
#define OFF_OPW  10813440
#define WTOT     15532032
#define PW_LEN   196608
#define XPW_LEN  786432
#define DTW_LEN  393216
#define REST_LEN 6094848   // PW + XPW + DTW + OPW
__device__ __half g_wh [WTOT];
__device__ __half g_ah [(size_t)MROWS * DI];
__device__ __half g_al [(size_t)MROWS * DI];
__device__ __half g_ph [(size_t)MROWS * 256];
__device__ __half g_pl [(size_t)MROWS * 256];
__device__ __half g_dbch[(size_t)MROWS * 64];   // cols 48..63 stay zero
__device__ __half g_dbcl[(size_t)MROWS * 64];

// ---------------- helpers ----------------
__device__ __forceinline__ float warp_sum(float v) {
#pragma unroll
    for (int o = 16; o; o >>= 1) v += __shfl_xor_sync(0xffffffffu, v, o);
    return v;
}
__device__ __forceinline__ float blk_sum(float v, float* sh) {
    int lane = threadIdx.x & 31, w = threadIdx.x >> 5;
    v = warp_sum(v);
    __syncthreads();
    if (lane == 0) sh[w] = v;
    __syncthreads();
    float t = (lane < 8) ? sh[lane] : 0.0f;
#pragma unroll
    for (int o = 4; o; o >>= 1) t += __shfl_xor_sync(0xffffffffu, t, o);
    return __shfl_sync(0xffffffffu, t, 0);
}
__device__ __forceinline__ uint32_t smem_u32(const void* p) {
    uint32_t a;
    asm("{ .reg .u64 t; cvta.to.shared.u64 t, %1; cvt.u32.u64 %0, t; }" : "=r"(a) : "l"(p));
    return a;
}
__device__ __forceinline__ void ldmx4(uint32_t addr, uint32_t& r0, uint32_t& r1,
                                      uint32_t& r2, uint32_t& r3) {
    asm volatile("ldmatrix.sync.aligned.m8n8.x4.shared.b16 {%0,%1,%2,%3}, [%4];"
                 : "=r"(r0), "=r"(r1), "=r"(r2), "=r"(r3) : "r"(addr));
}
__device__ __forceinline__ void mma16816(float* c, const uint32_t* a, uint32_t b0, uint32_t b1) {
    asm volatile(
        "mma.sync.aligned.m16n8k16.row.col.f32.f16.f16.f32 "
        "{%0,%1,%2,%3}, {%4,%5,%6,%7}, {%8,%9}, {%0,%1,%2,%3};"
        : "+f"(c[0]), "+f"(c[1]), "+f"(c[2]), "+f"(c[3])
        : "r"(a[0]), "r"(a[1]), "r"(a[2]), "r"(a[3]), "r"(b0), "r"(b1));
}
__device__ __forceinline__ void split_fp16(float v, __half& h, __half& l) {
    h = __float2half_rn(v);
    l = __float2half_rn(v - __half2float(h));
}

// ================= fp16 HMMA GEMM (r14 shape; Al optional 2nd product) =================
// CTA tile 128x128, BK=32, 512 threads (16 warps: 4m x 4n, warp tile 32x32).
// Reg-buffered gmem double-buffer, ks stagger. K mult of 32.
// C[M,N] = (Ah[+Al])[M,K] * Bh[N,K]^T, fp32 accum. Al == nullptr -> single product.
// mode: 0 plain, 1 +pb/ce, 2 +split to ehi/elo (n<48), 3 softplus(v + dtb[n])
#define TSTRIDE 40                 // halfs per smem row
#define TILE_B  10240              // 128*40*2 bytes
#define STAGE_B (3 * TILE_B)       // 30720 (Ah, Al, Bh)
#define GEMM_SMEM (2 * STAGE_B)    // 61440

__global__ void __launch_bounds__(512)
k_gemm_fp16(const __half* __restrict__ Ah, const __half* __restrict__ Al, int lda,
            const __half* __restrict__ Bh, int ldb,
            float* __restrict__ C, int ldc, int Ndim, int K,
            int mode, const float* __restrict__ pb, const float* __restrict__ ce,
            __half* __restrict__ ehi, __half* __restrict__ elo,
            const float* __restrict__ dtb) {
    extern __shared__ __align__(16) char sm[];
    uint32_t sbase = smem_u32(sm);
    const bool useAl = (Al != nullptr);

    int tid  = threadIdx.x;
    int wid  = tid >> 5;
    int lane = tid & 31;
    int bm = blockIdx.y * 128;
    int bn = blockIdx.x * 128;
    int warp_m = wid & 3;        // 0..3, 32 rows each
    int warp_n = wid >> 2;       // 0..3, 32 cols each
    int phase  = (wid >> 2) & 1;

    // loader: 512 threads; each thread loads 1 uint4 from each of Ah/[Al]/Bh
    int lrow = tid >> 2;           // 0..127
    int lq   = (tid & 3) * 8;      // col offset in halfs

    float acc[2][4][4];
#pragma unroll
    for (int i = 0; i < 2; i++)
#pragma unroll
        for (int j = 0; j < 4; j++)
#pragma unroll
            for (int q = 0; q < 4; q++) acc[i][j][q] = 0.0f;

    int arow = warp_m * 32 + (lane & 15);
    int brow = warp_n * 32 + (lane & 15);
    int koff0 = ((lane >> 4) * 8) * 2;     // bytes

    int nch = K >> 5;
    uint4 lvA, lvL, lvB;

    // prologue: chunk 0 -> regs -> stage 0
    lvA = *(const uint4*)(Ah + (size_t)(bm + lrow) * lda + lq);
    if (useAl) lvL = *(const uint4*)(Al + (size_t)(bm + lrow) * lda + lq);
    lvB = *(const uint4*)(Bh + (size_t)(bn + lrow) * ldb + lq);
    {
        uint32_t ro = (uint32_t)(lrow * TSTRIDE + lq) * 2;
        *(uint4*)(sm + ro) = lvA;
        if (useAl) *(uint4*)(sm + TILE_B + ro) = lvL;
        *(uint4*)(sm + 2 * TILE_B + ro) = lvB;
    }
    __syncthreads();

    for (int c = 0; c < nch; c++) {
        bool more = (c + 1 < nch);
        if (more) {
            int k0 = (c + 1) << 5;
            lvA = *(const uint4*)(Ah + (size_t)(bm + lrow) * lda + k0 + lq);
            if (useAl) lvL = *(const uint4*)(Al + (size_t)(bm + lrow) * lda + k0 + lq);
            lvB = *(const uint4*)(Bh + (size_t)(bn + lrow) * ldb + k0 + lq);
        }

        uint32_t stb = sbase + (c & 1) * STAGE_B;
#pragma unroll
        for (int ks = 0; ks < 2; ks++) {
            int kss = ks ^ phase;
            int kb = kss * 32 + koff0;
            uint32_t bh[2][4];
#pragma unroll
            for (int ng = 0; ng < 2; ng++) {
                uint32_t ob = stb + 2 * TILE_B + (uint32_t)((brow + ng * 16) * TSTRIDE) * 2 + kb;
                ldmx4(ob, bh[ng][0], bh[ng][1], bh[ng][2], bh[ng][3]);
            }
#pragma unroll
            for (int mt = 0; mt < 2; mt++) {
                uint32_t ah[4], al[4];
                uint32_t oa = stb + (uint32_t)((arow + mt * 16) * TSTRIDE) * 2 + kb;
                ldmx4(oa, ah[0], ah[1], ah[2], ah[3]);
                if (useAl) ldmx4(oa + TILE_B, al[0], al[1], al[2], al[3]);
#pragma unroll
                for (int nt = 0; nt < 4; nt++) {
                    int ng = nt >> 1, sel = nt & 1;
                    mma16816(acc[mt][nt], ah, bh[ng][sel], bh[ng][sel + 2]);
                    if (useAl) mma16816(acc[mt][nt], al, bh[ng][sel], bh[ng][sel + 2]);
                }
            }
        }

        if (more) {
            uint32_t d0 = ((c + 1) & 1) * STAGE_B;
            uint32_t ro = (uint32_t)(lrow * TSTRIDE + lq) * 2;
            *(uint4*)(sm + d0 + ro) = lvA;
            if (useAl) *(uint4*)(sm + d0 + TILE_B + ro) = lvL;
            *(uint4*)(sm + d0 + 2 * TILE_B + ro) = lvB;
        }
        __syncthreads();
    }

    // ---------- epilogue ----------
    int rg = lane >> 2;
    int cg = (lane & 3) * 2;
#pragma unroll
    for (int mt = 0; mt < 2; mt++) {
        int m = bm + warp_m * 32 + mt * 16 + rg;
#pragma unroll
        for (int nt = 0; nt < 4; nt++) {
            int n = bn + warp_n * 32 + nt * 8 + cg;
#pragma unroll
            for (int half = 0; half < 2; half++) {
                int mm = m + half * 8;
                float v0 = acc[mt][nt][half * 2];
                float v1 = acc[mt][nt][half * 2 + 1];
                if (mode == 1) {
                    int cc = (mm % LSEQ) & 7;
                    v0 += pb[n]     + ce[cc * DM + n];
                    v1 += pb[n + 1] + ce[cc * DM + n + 1];
                } else if (mode == 3) {
                    float a0 = v0 + dtb[n];
                    float a1 = v1 + dtb[n + 1];
                    v0 = (a0 > 20.0f) ? a0 : log1pf(expf(a0));
                    v1 = (a1 > 20.0f) ? a1 : log1pf(expf(a1));
                }
                if (n < Ndim)
                    *(float2*)(C + (size_t)mm * ldc + n) = make_float2(v0, v1);
                if (mode == 2 && n < 48) {
                    __half h0, l0, h1, l1;
                    split_fp16(v0, h0, l0);
                    split_fp16(v1, h1, l1);
                    size_t eo = (size_t)mm * 64 + n;
                    ehi[eo] = h0; ehi[eo + 1] = h1;
                    elo[eo] = l0; elo[eo + 1] = l1;
                }
            }
        }
    }
}

// ---------------- weight convert: big ipw -> fp16 ----------------
__global__ void k_splitw(const float* __restrict__ src, __half* __restrict__ hi, size_t n) {
    size_t idx = (size_t)blockIdx.x * 256 + threadIdx.x;
    if (idx >= n) return;
    hi[idx] = __float2half_rn(src[idx]);
}

// ---------------- weight convert: pw + xpw(pad rows) + dtw(pad cols) + opw ----------------
__global__ void k_splitw_rest(const float* __restrict__ pw, const float* __restrict__ xpw,
                              const float* __restrict__ dtw, const float* __restrict__ opw,
                              __half* __restrict__ hi) {
    size_t idx = (size_t)blockIdx.x * 256 + threadIdx.x;
    if (idx >= (size_t)REST_LEN) return;
    float v; size_t out;
    if (idx < PW_LEN) {
        v = pw[idx];
        out = OFF_PW + idx;
    } else if (idx < (size_t)PW_LEN + XPW_LEN) {
        size_t i2 = idx - PW_LEN;
        int lay = (int)(i2 / 196608);
        int w   = (int)(i2 % 196608);
        int r = w / 1536, cc = w % 1536;
        v = (r < 80) ? xpw[(size_t)lay * 122880 + (size_t)r * 1536 + cc] : 0.0f;
        out = OFF_XPW + i2;
    } else if (idx < (size_t)PW_LEN + XPW_LEN + DTW_LEN) {
        size_t i3 = idx - PW_LEN - XPW_LEN;
        int lay = (int)(i3 / 98304);
        int w   = (int)(i3 % 98304);
        int r = w >> 6, cc = w & 63;
        v = (cc < 48) ? dtw[(size_t)lay * 73728 + (size_t)r * 48 + cc] : 0.0f;
        out = OFF_DTW + i3;
    } else {
        size_t i4 = idx - PW_LEN - XPW_LEN - DTW_LEN;
        v = opw[i4];
        out = OFF_OPW + i4;
    }
    hi[out] = __float2half_rn(v);
}

// ---------------- im2col -> fp16 ----------------
__global__ void k_im2col(const float* __restrict__ x, __half* __restrict__ hi) {
    int row = blockIdx.x;
    int k   = threadIdx.x;
    int l  = row % LSEQ;
    int b  = row / LSEQ;
    int c  = l & 7;
    int hw = l >> 3;
    int wg = hw % HGRID;
    int hg = hw / HGRID;
    int p  = k >> 4;
    int q  = k & 15;
    float v = x[(((size_t)(b * IN_CH + c) * IMG) + (hg * PATCHSZ + p)) * IMG + (wg * PATCHSZ + q)];
    hi[(size_t)row * 256 + k] = __float2half_rn(v);
}

// ---------------- residual + LayerNorm (768) -> fp16 or fp32 ----------------
__global__ void k_resid_ln(const float* __restrict__ hid, float* __restrict__ res,
                           float* __restrict__ hn,
                           __half* __restrict__ ohi,
                           const float* __restrict__ w, const float* __restrict__ b,
                           int first, int tofp16) {
    __shared__ float sh[8];
    int row = blockIdx.x;
    float v[3];
#pragma unroll
    for (int j = 0; j < 3; j++) {
        int c = threadIdx.x + j * 256;
        size_t idx = (size_t)row * DM + c;
        float r = first ? hid[idx] : (res[idx] + hid[idx]);
        res[idx] = r;
        v[j] = r;
    }
    float mean = blk_sum(v[0] + v[1] + v[2], sh) * (1.0f / DM);
    float sq = 0.f;
#pragma unroll
    for (int j = 0; j < 3; j++) { v[j] -= mean; sq += v[j] * v[j]; }
    float var = blk_sum(sq, sh) * (1.0f / DM);
    float iv = rsqrtf(var + EPS_LN);
#pragma unroll
    for (int j = 0; j < 3; j++) {
        int c = threadIdx.x + j * 256;
        size_t idx = (size_t)row * DM + c;
        float o = v[j] * iv * w[c] + b[c];
        if (tofp16) {
            ohi[idx] = __float2half_rn(o);
        } else {
            hn[idx] = o;
        }
    }
}

// ---------------- depthwise conv(4) + SiLU -> fp32 + fp16 hi/lo ----------------
__global__ void k_conv_silu(const float* __restrict__ xz, const float* __restrict__ cw,
                            const float* __restrict__ cb, float* __restrict__ xc,
                            __half* __restrict__ ohi, __half* __restrict__ olo) {
    size_t idx = (size_t)blockIdx.x * 256 + threadIdx.x;
    if (idx >= (size_t)MROWS * DI) return;
    int e   = (int)(idx % DI);
    int row = (int)(idx / DI);
    int l   = row % LSEQ;
    float acc = cb[e];
    const float* cwp = cw + e * 4;
    size_t base = (size_t)row * (2 * DI) + e;
#pragma unroll
    for (int k = 0; k < 4; k++) {
        int ls = l - 3 + k;
        if (ls >= 0) acc += xz[base + (size_t)(k - 3) * (2 * DI)] * cwp[k];
    }
    float o = acc / (1.0f + expf(-acc));
    xc[idx] = o;
    __half h, lo_;
    split_fp16(o, h, lo_);
    ohi[idx] = h; olo[idx] = lo_;
}

// ---------------- selective scan, SMEM-tiled ----------------
#define SCH 64
#define STT 32
__global__ void __launch_bounds__(256)
k_scan(const float* __restrict__ dt, const float* __restrict__ xc,
       const float* __restrict__ dbc, const float* __restrict__ Alog,
       float* __restrict__ y) {
    __shared__ float sdt[STT][SCH];
    __shared__ float sxc[STT][SCH];
    __shared__ float sB[STT][16];
    __shared__ float sC[STT][16];

    int b  = blockIdx.y;
    int d0 = blockIdx.x * SCH;
    int tid = threadIdx.x;
    int ng  = tid & 3;
    int chl = tid >> 2;          // 0..63
    int d   = d0 + chl;

    float A0 = -expf(Alog[d * DS + ng * 4 + 0]);
    float A1 = -expf(Alog[d * DS + ng * 4 + 1]);
    float A2 = -expf(Alog[d * DS + ng * 4 + 2]);
    float A3 = -expf(Alog[d * DS + ng * 4 + 3]);

    float h0 = 0.f, h1 = 0.f, h2 = 0.f, h3 = 0.f;
    int rowbase = b * LSEQ;

    for (int t0 = 0; t0 < LSEQ; t0 += STT) {
        __syncthreads();
#pragma unroll
        for (int i = 0; i < 8; i++) {
            int id = tid + i * 256;          // 0..2047
            int tt = id >> 6, cc = id & 63;
            size_t g = (size_t)(rowbase + t0 + tt) * DI + d0 + cc;
            sdt[tt][cc] = dt[g];
            sxc[tt][cc] = xc[g];
        }
#pragma unroll
        for (int i = 0; i < 2; i++) {
            int id = tid + i * 256;          // 0..511
            int tt = id >> 4, nn = id & 15;
            const float* base = dbc + (size_t)(rowbase + t0 + tt) * 80;
            sB[tt][nn] = base[48 + nn];
            sC[tt][nn] = base[64 + nn];
        }
        __syncthreads();

#pragma unroll 4
        for (int tt = 0; tt < STT; tt++) {
            float dtv = sdt[tt][chl];
            float u = dtv * sxc[tt][chl];
            h0 = __expf(dtv * A0) * h0 + u * sB[tt][ng * 4 + 0];
            h1 = __expf(dtv * A1) * h1 + u * sB[tt][ng * 4 + 1];
            h2 = __expf(dtv * A2) * h2 + u * sB[tt][ng * 4 + 2];
            h3 = __expf(dtv * A3) * h3 + u * sB[tt][ng * 4 + 3];
            float p = h0 * sC[tt][ng * 4 + 0] + h1 * sC[tt][ng * 4 + 1]
                    + h2 * sC[tt][ng * 4 + 2] + h3 * sC[tt][ng * 4 + 3];
            p += __shfl_xor_sync(0xffffffffu, p, 1);
            p += __shfl_xor_sync(0xffffffffu, p, 2);
            if (ng == 0) y[(size_t)(rowbase + t0 + tt) * DI + d] = p;
        }
    }
}

// ---------------- y = LN(y + D*x) * silu(z) -> fp16 ----------------
__global__ void k_ypost(const float* __restrict__ y, const float* __restrict__ xc,
                        const float* __restrict__ xz, const float* __restrict__ Dp,
                        const float* __restrict__ snw, const float* __restrict__ snb,
                        __half* __restrict__ ohi) {
    __shared__ float sh[8];
    int row = blockIdx.x;
    float v[6];
#pragma unroll
    for (int j = 0; j < 6; j++) {
        int c = threadIdx.x + j * 256;
        size_t idx = (size_t)row * DI + c;
        v[j] = y[idx] + Dp[c] * xc[idx];
    }
    float s = 0.f;
#pragma unroll
    for (int j = 0; j < 6; j++) s += v[j];
    float mean = blk_sum(s, sh) * (1.0f / DI);
    float sq = 0.f;
#pragma unroll
    for (int j = 0; j < 6; j++) { v[j] -= mean; sq += v[j] * v[j]; }
    float var = blk_sum(sq, sh) * (1.0f / DI);
    float iv = rsqrtf(var + EPS_LN);
#pragma unroll
    for (int j = 0; j < 6; j++) {
        int c = threadIdx.x + j * 256;
        float nv = v[j] * iv * snw[c] + snb[c];
        float z = xz[(size_t)row * (2 * DI) + DI + c];
        float o = nv * (z / (1.0f + expf(-z)));
        ohi[(size_t)row * DI + c] = __float2half_rn(o);
    }
}

// ---------------- mean-pool partial sums ----------------
__global__ void k_pool(const float* __restrict__ hn, float* __restrict__ pool) {
    int b = blockIdx.x;
    int chunk = blockIdx.y;
#pragma unroll
    for (int j = 0; j < 3; j++) {
        int d = threadIdx.x + j * 256;
        float s = 0.f;
        int l0 = chunk * 112;
        for (int l = l0; l < l0 + 112; l++)
            s += hn[((size_t)(b * LSEQ + l)) * DM + d];
        atomicAdd(&pool[b * DM + d], s);
    }
}

// ---------------- head ----------------
__global__ void k_head(const float* __restrict__ pool, const float* __restrict__ hw,
                       const float* __restrict__ hb, float* __restrict__ out) {
    int cls = blockIdx.x;
    int b   = threadIdx.x >> 5;
    int lane = threadIdx.x & 31;
    float s = 0.f;
    for (int d = lane; d < DM; d += 32)
        s += pool[b * DM + d] * hw[(size_t)cls * DM + d];
    s = warp_sum(s);
    if (lane == 0)
        out[b * NC + cls] = s * (1.0f / (float)LSEQ) + hb[cls];
}

// ---------------- launch ----------------
extern "C" void kernel_launch(void* const* d_in, const int* in_sizes, int n_in,
                              void* d_out, int out_size) {
    const float* x      = (const float*)d_in[0];
    const float* pw     = (const float*)d_in[1];
    const float* pb     = (const float*)d_in[2];
    const float* ce     = (const float*)d_in[3];
    const float* nw     = (const float*)d_in[4];
    const float* nb     = (const float*)d_in[5];
    const float* ipw    = (const float*)d_in[6];
    const float* cw     = (const float*)d_in[7];
    const float* cb     = (const float*)d_in[8];
    const float* xpw    = (const float*)d_in[9];
    const float* dtw    = (const float*)d_in[10];
    const float* dtb    = (const float*)d_in[11];
    const float* alog   = (const float*)d_in[12];
    const float* Dp     = (const float*)d_in[13];
    const float* snw    = (const float*)d_in[14];
    const float* snb    = (const float*)d_in[15];
    const float* opw    = (const float*)d_in[16];
    const float* nfw    = (const float*)d_in[17];
    const float* nfb    = (const float*)d_in[18];
    const float* hw     = (const float*)d_in[19];
    const float* hb     = (const float*)d_in[20];
    float* out = (float*)d_out;

    float *res, *hid, *hn, *xz, *xc, *dbc, *dtbuf, *ybuf, *pool;
    __half *wh, *ah, *al, *ph, *dbch, *dbcl;
    cudaGetSymbolAddress((void**)&res,   g_res);
    cudaGetSymbolAddress((void**)&hid,   g_hid);
    cudaGetSymbolAddress((void**)&hn,    g_hn);
    cudaGetSymbolAddress((void**)&xz,    g_xz);
    cudaGetSymbolAddress((void**)&xc,    g_xc);
    cudaGetSymbolAddress((void**)&dbc,   g_dbc);
    cudaGetSymbolAddress((void**)&dtbuf, g_dt);
    cudaGetSymbolAddress((void**)&ybuf,  g_y);
    cudaGetSymbolAddress((void**)&pool,  g_pool);
    cudaGetSymbolAddress((void**)&wh,    g_wh);
    cudaGetSymbolAddress((void**)&ah,    g_ah);
    cudaGetSymbolAddress((void**)&al,    g_al);
    cudaGetSymbolAddress((void**)&ph,    g_ph);
    cudaGetSymbolAddress((void**)&dbch,  g_dbch);
    cudaGetSymbolAddress((void**)&dbcl,  g_dbcl);

    cudaFuncSetAttribute(k_gemm_fp16, cudaFuncAttributeMaxDynamicSharedMemorySize, GEMM_SMEM);

    const int ew_di = (int)(((size_t)MROWS * DI + 255) / 256);
    const int MB = MROWS / 128;   // 98

    // launch 1: big ipw convert
    k_splitw<<<(int)(((size_t)12288 * 768 + 255) / 256), 256>>>(
        ipw, wh + OFF_IPW, (size_t)12288 * 768);
    // launch 2: all other weight converts
    k_splitw_rest<<<(REST_LEN + 255) / 256, 256>>>(pw, xpw, dtw, opw, wh);
    // launch 3: im2col (fp16 only; patch gemm runs single-product)
    k_im2col<<<MROWS, 256>>>(x, ph);
    // launch 4: patch gemm (bias + channel-embed fused, mode 1, no Al)
    k_gemm_fp16<<<dim3(6, MB), 512, GEMM_SMEM>>>(ph, nullptr, 256,
        wh + OFF_PW, 256, hid, DM, DM, 256, 1, pb, ce, nullptr, nullptr, nullptr);

    for (int i = 0; i < DEPTH; i++) {
        // launch 5 (i=0): resid_ln; launch 6 (i=0): in_proj gemm  <- profiled by -s 5 -c 1
        k_resid_ln<<<MROWS, 256>>>(hid, res, nullptr, ah,
                                   nw + i * DM, nb + i * DM, i == 0 ? 1 : 0, 1);
        // in_proj: single-product fp16
        k_gemm_fp16<<<dim3(24, MB), 512, GEMM_SMEM>>>(ah, nullptr, DM,
            wh + OFF_IPW + (size_t)i * 3072 * 768, DM,
            xz, 3072, 3072, DM, 0, nullptr, nullptr, nullptr, nullptr, nullptr);
        k_conv_silu<<<ew_di, 256>>>(xz, cw + (size_t)i * DI * 4, cb + i * DI, xc, ah, al);
        // x_proj: keep 2-product (feeds scan B/C + dt)
        k_gemm_fp16<<<dim3(1, MB), 512, GEMM_SMEM>>>(ah, al, DI,
            wh + OFF_XPW + (size_t)i * 128 * 1536, DI,
            dbc, 80, 80, DI, 2, nullptr, nullptr, dbch, dbcl, nullptr);
        // dt gemm: keep 2-product, fused softplus+bias (mode 3)
        k_gemm_fp16<<<dim3(12, MB), 512, GEMM_SMEM>>>(dbch, dbcl, 64,
            wh + OFF_DTW + (size_t)i * 1536 * 64, 64,
            dtbuf, DI, DI, 64, 3, nullptr, nullptr, nullptr, nullptr, dtb + i * DI);
        k_scan<<<dim3(DI / SCH, BATCH), 256>>>(dtbuf, xc, dbc,
                                               alog + (size_t)i * DI * DS, ybuf);
        k_ypost<<<MROWS, 256>>>(ybuf, xc, xz, Dp + i * DI, snw + i * DI, snb + i * DI, ah);
        // out_proj: single-product fp16
        k_gemm_fp16<<<dim3(6, MB), 512, GEMM_SMEM>>>(ah, nullptr, DI,
            wh + OFF_OPW + (size_t)i * 768 * 1536, DI,
            hid, DM, DM, DI, 0, nullptr, nullptr, nullptr, nullptr, nullptr);
    }

    // final residual + LN + pool + head
    k_resid_ln<<<MROWS, 256>>>(hid, res, hn, nullptr, nfw, nfb, 0, 0);
    cudaMemsetAsync(pool, 0, BATCH * DM * sizeof(float));
    k_pool<<<dim3(BATCH, 14), 256>>>(hn, pool);
    k_head<<<NC, 256>>>(pool, hw, hb, out);
}

// round 17
// speedup vs baseline: 1.3783x; 1.2606x over previous
#include <cuda_runtime.h>
#include <cuda_fp16.h>
#include <math.h>
#include <stdint.h>

#define BATCH   8
#define IN_CH   8
#define IMG     224
#define PATCHSZ 16
#define HGRID   14
#define LSEQ    1568            // 14*14*8
#define MROWS   12544           // BATCH*LSEQ = 98*128
#define DM      768
#define DI      1536
#define DS      16
#define DR      48
#define NC      1000
#define DEPTH   4
#define EPS_LN  1e-5f

// ---------------- device scratch ----------------
__device__ float g_res  [(size_t)MROWS * DM];
__device__ float g_hid  [(size_t)MROWS * DM];
__device__ float g_hn   [(size_t)MROWS * DM];
__device__ float g_xz   [(size_t)MROWS * 2 * DI];
__device__ float g_xc   [(size_t)MROWS * DI];
__device__ float g_dbc  [(size_t)MROWS * 80];
__device__ float g_dt   [(size_t)MROWS * DI];
__device__ float g_y    [(size_t)MROWS * DI];
__device__ float g_pool [BATCH * DM];

// fp16 buffers
#define OFF_PW   0
#define OFF_IPW  196608
#define OFF_XPW  9633792
#define OFF_DTW  10420224
#define OFF_OPW  10813440
#define WTOT     15532032
#define PW_LEN   196608
#define XPW_LEN  786432
#define DTW_LEN  393216
#define REST_LEN 6094848   // PW + XPW + DTW + OPW
__device__ __half g_wh [WTOT];
__device__ __half g_ah [(size_t)MROWS * DI];
__device__ __half g_al [(size_t)MROWS * DI];
__device__ __half g_ph [(size_t)MROWS * 256];
__device__ __half g_dbch[(size_t)MROWS * 64];   // cols 48..63 stay zero
__device__ __half g_dbcl[(size_t)MROWS * 64];

// ---------------- helpers ----------------
__device__ __forceinline__ float warp_sum(float v) {
#pragma unroll
    for (int o = 16; o; o >>= 1) v += __shfl_xor_sync(0xffffffffu, v, o);
    return v;
}
__device__ __forceinline__ float blk_sum(float v, float* sh) {
    int lane = threadIdx.x & 31, w = threadIdx.x >> 5;
    v = warp_sum(v);
    __syncthreads();
    if (lane == 0) sh[w] = v;
    __syncthreads();
    float t = (lane < 8) ? sh[lane] : 0.0f;
#pragma unroll
    for (int o = 4; o; o >>= 1) t += __shfl_xor_sync(0xffffffffu, t, o);
    return __shfl_sync(0xffffffffu, t, 0);
}
__device__ __forceinline__ uint32_t smem_u32(const void* p) {
    uint32_t a;
    asm("{ .reg .u64 t; cvta.to.shared.u64 t, %1; cvt.u32.u64 %0, t; }" : "=r"(a) : "l"(p));
    return a;
}
__device__ __forceinline__ void ldmx4(uint32_t addr, uint32_t& r0, uint32_t& r1,
                                      uint32_t& r2, uint32_t& r3) {
    asm volatile("ldmatrix.sync.aligned.m8n8.x4.shared.b16 {%0,%1,%2,%3}, [%4];"
                 : "=r"(r0), "=r"(r1), "=r"(r2), "=r"(r3) : "r"(addr));
}
__device__ __forceinline__ void mma16816(float* c, const uint32_t* a, uint32_t b0, uint32_t b1) {
    asm volatile(
        "mma.sync.aligned.m16n8k16.row.col.f32.f16.f16.f32 "
        "{%0,%1,%2,%3}, {%4,%5,%6,%7}, {%8,%9}, {%0,%1,%2,%3};"
        : "+f"(c[0]), "+f"(c[1]), "+f"(c[2]), "+f"(c[3])
        : "r"(a[0]), "r"(a[1]), "r"(a[2]), "r"(a[3]), "r"(b0), "r"(b1));
}
__device__ __forceinline__ void split_fp16(float v, __half& h, __half& l) {
    h = __float2half_rn(v);
    l = __float2half_rn(v - __half2float(h));
}

// ================= fp16 HMMA GEMM, templated N-tile =================
// NT=128: warp tile 32x32, optional 2nd product Al (r16-proven path).
// NT=256: warp tile 32x64, single product; same stage bytes, half the chunks.
// CTA tile 128xNT, BK=32, 512 threads. Reg-buffered gmem double-buffer, ks stagger.
// C[M,N] = (Ah[+Al])[M,K] * Bh[N,K]^T, fp32 accum. K mult of 32.
// mode: 0 plain, 1 +pb/ce, 2 +split to ehi/elo (n<48), 3 softplus(v + dtb[n])
#define TSTRIDE 40                 // halfs per smem row
#define TILE_B  10240              // 128*40*2 bytes
#define STAGE_B (3 * TILE_B)       // 30720 (either A+Al+B128 or A+B256)
#define GEMM_SMEM (2 * STAGE_B)    // 61440

template<int NT>
__global__ void __launch_bounds__(512)
k_gemm_fp16(const __half* __restrict__ Ah, const __half* __restrict__ Al, int lda,
            const __half* __restrict__ Bh, int ldb,
            float* __restrict__ C, int ldc, int Ndim, int K,
            int mode, const float* __restrict__ pb, const float* __restrict__ ce,
            __half* __restrict__ ehi, __half* __restrict__ elo,
            const float* __restrict__ dtb) {
    extern __shared__ __align__(16) char sm[];
    uint32_t sbase = smem_u32(sm);
    const bool useAl = (NT == 128) && (Al != nullptr);
    constexpr int BOFF = (NT == 128) ? 2 * TILE_B : TILE_B;   // B tile smem offset
    constexpr int NG   = NT / 64;    // B ldsm groups per warp (2 or 4)
    constexpr int NTL  = NT / 32;    // n-subtiles per warp (4 or 8)

    int tid  = threadIdx.x;
    int wid  = tid >> 5;
    int lane = tid & 31;
    int bm = blockIdx.y * 128;
    int bn = blockIdx.x * NT;
    int warp_m = wid & 3;            // 0..3, 32 rows each
    int warp_n = wid >> 2;           // 0..3, NT/4 cols each
    int phase  = (wid >> 2) & 1;

    // loader: A rows tid>>2 (1 uint4); B rows tid>>2 [+128 for NT=256]
    int lrow = tid >> 2;             // 0..127
    int lq   = (tid & 3) * 8;        // col offset in halfs

    float acc[2][NTL][4];
#pragma unroll
    for (int i = 0; i < 2; i++)
#pragma unroll
        for (int j = 0; j < NTL; j++)
#pragma unroll
            for (int q = 0; q < 4; q++) acc[i][j][q] = 0.0f;

    int arow = warp_m * 32 + (lane & 15);
    int brow = warp_n * (NT / 4) + (lane & 15);
    int koff0 = ((lane >> 4) * 8) * 2;     // bytes

    int nch = K >> 5;
    uint4 lvA, lvL, lvB0, lvB1;

    // prologue: chunk 0 -> regs -> stage 0
    lvA = *(const uint4*)(Ah + (size_t)(bm + lrow) * lda + lq);
    if (useAl) lvL = *(const uint4*)(Al + (size_t)(bm + lrow) * lda + lq);
    lvB0 = *(const uint4*)(Bh + (size_t)(bn + lrow) * ldb + lq);
    if (NT == 256) lvB1 = *(const uint4*)(Bh + (size_t)(bn + 128 + lrow) * ldb + lq);
    {
        uint32_t ro = (uint32_t)(lrow * TSTRIDE + lq) * 2;
        *(uint4*)(sm + ro) = lvA;
        if (useAl) *(uint4*)(sm + TILE_B + ro) = lvL;
        *(uint4*)(sm + BOFF + ro) = lvB0;
        if (NT == 256) *(uint4*)(sm + BOFF + TILE_B + ro) = lvB1;
    }
    __syncthreads();

    for (int c = 0; c < nch; c++) {
        bool more = (c + 1 < nch);
        if (more) {
            int k0 = (c + 1) << 5;
            lvA = *(const uint4*)(Ah + (size_t)(bm + lrow) * lda + k0 + lq);
            if (useAl) lvL = *(const uint4*)(Al + (size_t)(bm + lrow) * lda + k0 + lq);
            lvB0 = *(const uint4*)(Bh + (size_t)(bn + lrow) * ldb + k0 + lq);
            if (NT == 256) lvB1 = *(const uint4*)(Bh + (size_t)(bn + 128 + lrow) * ldb + k0 + lq);
        }

        uint32_t stb = sbase + (c & 1) * STAGE_B;
#pragma unroll
        for (int ks = 0; ks < 2; ks++) {
            int kss = ks ^ phase;
            int kb = kss * 32 + koff0;
            uint32_t bh[NG][4];
#pragma unroll
            for (int ng = 0; ng < NG; ng++) {
                uint32_t ob = stb + BOFF + (uint32_t)((brow + ng * 16) * TSTRIDE) * 2 + kb;
                ldmx4(ob, bh[ng][0], bh[ng][1], bh[ng][2], bh[ng][3]);
            }
#pragma unroll
            for (int mt = 0; mt < 2; mt++) {
                uint32_t ah[4], al[4];
                uint32_t oa = stb + (uint32_t)((arow + mt * 16) * TSTRIDE) * 2 + kb;
                ldmx4(oa, ah[0], ah[1], ah[2], ah[3]);
                if (useAl) ldmx4(oa + TILE_B, al[0], al[1], al[2], al[3]);
#pragma unroll
                for (int nt = 0; nt < NTL; nt++) {
                    int ng = nt >> 1, sel = nt & 1;
                    mma16816(acc[mt][nt], ah, bh[ng][sel], bh[ng][sel + 2]);
                    if (useAl) mma16816(acc[mt][nt], al, bh[ng][sel], bh[ng][sel + 2]);
                }
            }
        }

        if (more) {
            uint32_t d0 = ((c + 1) & 1) * STAGE_B;
            uint32_t ro = (uint32_t)(lrow * TSTRIDE + lq) * 2;
            *(uint4*)(sm + d0 + ro) = lvA;
            if (useAl) *(uint4*)(sm + d0 + TILE_B + ro) = lvL;
            *(uint4*)(sm + d0 + BOFF + ro) = lvB0;
            if (NT == 256) *(uint4*)(sm + d0 + BOFF + TILE_B + ro) = lvB1;
        }
        __syncthreads();
    }

    // ---------- epilogue ----------
    int rg = lane >> 2;
    int cg = (lane & 3) * 2;
#pragma unroll
    for (int mt = 0; mt < 2; mt++) {
        int m = bm + warp_m * 32 + mt * 16 + rg;
#pragma unroll
        for (int nt = 0; nt < NTL; nt++) {
            int n = bn + warp_n * (NT / 4) + nt * 8 + cg;
#pragma unroll
            for (int half = 0; half < 2; half++) {
                int mm = m + half * 8;
                float v0 = acc[mt][nt][half * 2];
                float v1 = acc[mt][nt][half * 2 + 1];
                if (mode == 1) {
                    int cc = (mm % LSEQ) & 7;
                    v0 += pb[n]     + ce[cc * DM + n];
                    v1 += pb[n + 1] + ce[cc * DM + n + 1];
                } else if (mode == 3) {
                    float a0 = v0 + dtb[n];
                    float a1 = v1 + dtb[n + 1];
                    v0 = (a0 > 20.0f) ? a0 : log1pf(expf(a0));
                    v1 = (a1 > 20.0f) ? a1 : log1pf(expf(a1));
                }
                if (n < Ndim)
                    *(float2*)(C + (size_t)mm * ldc + n) = make_float2(v0, v1);
                if (mode == 2 && n < 48) {
                    __half h0, l0, h1, l1;
                    split_fp16(v0, h0, l0);
                    split_fp16(v1, h1, l1);
                    size_t eo = (size_t)mm * 64 + n;
                    ehi[eo] = h0; ehi[eo + 1] = h1;
                    elo[eo] = l0; elo[eo + 1] = l1;
                }
            }
        }
    }
}

// ---------------- weight convert: big ipw -> fp16 ----------------
__global__ void k_splitw(const float* __restrict__ src, __half* __restrict__ hi, size_t n) {
    size_t idx = (size_t)blockIdx.x * 256 + threadIdx.x;
    if (idx >= n) return;
    hi[idx] = __float2half_rn(src[idx]);
}

// ---------------- weight convert: pw + xpw(pad rows) + dtw(pad cols) + opw ----------------
__global__ void k_splitw_rest(const float* __restrict__ pw, const float* __restrict__ xpw,
                              const float* __restrict__ dtw, const float* __restrict__ opw,
                              __half* __restrict__ hi) {
    size_t idx = (size_t)blockIdx.x * 256 + threadIdx.x;
    if (idx >= (size_t)REST_LEN) return;
    float v; size_t out;
    if (idx < PW_LEN) {
        v = pw[idx];
        out = OFF_PW + idx;
    } else if (idx < (size_t)PW_LEN + XPW_LEN) {
        size_t i2 = idx - PW_LEN;
        int lay = (int)(i2 / 196608);
        int w   = (int)(i2 % 196608);
        int r = w / 1536, cc = w % 1536;
        v = (r < 80) ? xpw[(size_t)lay * 122880 + (size_t)r * 1536 + cc] : 0.0f;
        out = OFF_XPW + i2;
    } else if (idx < (size_t)PW_LEN + XPW_LEN + DTW_LEN) {
        size_t i3 = idx - PW_LEN - XPW_LEN;
        int lay = (int)(i3 / 98304);
        int w   = (int)(i3 % 98304);
        int r = w >> 6, cc = w & 63;
        v = (cc < 48) ? dtw[(size_t)lay * 73728 + (size_t)r * 48 + cc] : 0.0f;
        out = OFF_DTW + i3;
    } else {
        size_t i4 = idx - PW_LEN - XPW_LEN - DTW_LEN;
        v = opw[i4];
        out = OFF_OPW + i4;
    }
    hi[out] = __float2half_rn(v);
}

// ---------------- im2col -> fp16 ----------------
__global__ void k_im2col(const float* __restrict__ x, __half* __restrict__ hi) {
    int row = blockIdx.x;
    int k   = threadIdx.x;
    int l  = row % LSEQ;
    int b  = row / LSEQ;
    int c  = l & 7;
    int hw = l >> 3;
    int wg = hw % HGRID;
    int hg = hw / HGRID;
    int p  = k >> 4;
    int q  = k & 15;
    float v = x[(((size_t)(b * IN_CH + c) * IMG) + (hg * PATCHSZ + p)) * IMG + (wg * PATCHSZ + q)];
    hi[(size_t)row * 256 + k] = __float2half_rn(v);
}

// ---------------- residual + LayerNorm (768) -> fp16 or fp32 ----------------
__global__ void k_resid_ln(const float* __restrict__ hid, float* __restrict__ res,
                           float* __restrict__ hn,
                           __half* __restrict__ ohi,
                           const float* __restrict__ w, const float* __restrict__ b,
                           int first, int tofp16) {
    __shared__ float sh[8];
    int row = blockIdx.x;
    float v[3];
#pragma unroll
    for (int j = 0; j < 3; j++) {
        int c = threadIdx.x + j * 256;
        size_t idx = (size_t)row * DM + c;
        float r = first ? hid[idx] : (res[idx] + hid[idx]);
        res[idx] = r;
        v[j] = r;
    }
    float mean = blk_sum(v[0] + v[1] + v[2], sh) * (1.0f / DM);
    float sq = 0.f;
#pragma unroll
    for (int j = 0; j < 3; j++) { v[j] -= mean; sq += v[j] * v[j]; }
    float var = blk_sum(sq, sh) * (1.0f / DM);
    float iv = rsqrtf(var + EPS_LN);
#pragma unroll
    for (int j = 0; j < 3; j++) {
        int c = threadIdx.x + j * 256;
        size_t idx = (size_t)row * DM + c;
        float o = v[j] * iv * w[c] + b[c];
        if (tofp16) {
            ohi[idx] = __float2half_rn(o);
        } else {
            hn[idx] = o;
        }
    }
}

// ---------------- depthwise conv(4) + SiLU -> fp32 + fp16 hi/lo ----------------
__global__ void k_conv_silu(const float* __restrict__ xz, const float* __restrict__ cw,
                            const float* __restrict__ cb, float* __restrict__ xc,
                            __half* __restrict__ ohi, __half* __restrict__ olo) {
    size_t idx = (size_t)blockIdx.x * 256 + threadIdx.x;
    if (idx >= (size_t)MROWS * DI) return;
    int e   = (int)(idx % DI);
    int row = (int)(idx / DI);
    int l   = row % LSEQ;
    float acc = cb[e];
    const float* cwp = cw + e * 4;
    size_t base = (size_t)row * (2 * DI) + e;
#pragma unroll
    for (int k = 0; k < 4; k++) {
        int ls = l - 3 + k;
        if (ls >= 0) acc += xz[base + (size_t)(k - 3) * (2 * DI)] * cwp[k];
    }
    float o = acc / (1.0f + expf(-acc));
    xc[idx] = o;
    __half h, lo_;
    split_fp16(o, h, lo_);
    ohi[idx] = h; olo[idx] = lo_;
}

// ---------------- selective scan, SMEM-tiled ----------------
#define SCH 64
#define STT 32
__global__ void __launch_bounds__(256)
k_scan(const float* __restrict__ dt, const float* __restrict__ xc,
       const float* __restrict__ dbc, const float* __restrict__ Alog,
       float* __restrict__ y) {
    __shared__ float sdt[STT][SCH];
    __shared__ float sxc[STT][SCH];
    __shared__ float sB[STT][16];
    __shared__ float sC[STT][16];

    int b  = blockIdx.y;
    int d0 = blockIdx.x * SCH;
    int tid = threadIdx.x;
    int ng  = tid & 3;
    int chl = tid >> 2;          // 0..63
    int d   = d0 + chl;

    float A0 = -expf(Alog[d * DS + ng * 4 + 0]);
    float A1 = -expf(Alog[d * DS + ng * 4 + 1]);
    float A2 = -expf(Alog[d * DS + ng * 4 + 2]);
    float A3 = -expf(Alog[d * DS + ng * 4 + 3]);

    float h0 = 0.f, h1 = 0.f, h2 = 0.f, h3 = 0.f;
    int rowbase = b * LSEQ;

    for (int t0 = 0; t0 < LSEQ; t0 += STT) {
        __syncthreads();
#pragma unroll
        for (int i = 0; i < 8; i++) {
            int id = tid + i * 256;          // 0..2047
            int tt = id >> 6, cc = id & 63;
            size_t g = (size_t)(rowbase + t0 + tt) * DI + d0 + cc;
            sdt[tt][cc] = dt[g];
            sxc[tt][cc] = xc[g];
        }
#pragma unroll
        for (int i = 0; i < 2; i++) {
            int id = tid + i * 256;          // 0..511
            int tt = id >> 4, nn = id & 15;
            const float* base = dbc + (size_t)(rowbase + t0 + tt) * 80;
            sB[tt][nn] = base[48 + nn];
            sC[tt][nn] = base[64 + nn];
        }
        __syncthreads();

#pragma unroll 4
        for (int tt = 0; tt < STT; tt++) {
            float dtv = sdt[tt][chl];
            float u = dtv * sxc[tt][chl];
            h0 = __expf(dtv * A0) * h0 + u * sB[tt][ng * 4 + 0];
            h1 = __expf(dtv * A1) * h1 + u * sB[tt][ng * 4 + 1];
            h2 = __expf(dtv * A2) * h2 + u * sB[tt][ng * 4 + 2];
            h3 = __expf(dtv * A3) * h3 + u * sB[tt][ng * 4 + 3];
            float p = h0 * sC[tt][ng * 4 + 0] + h1 * sC[tt][ng * 4 + 1]
                    + h2 * sC[tt][ng * 4 + 2] + h3 * sC[tt][ng * 4 + 3];
            p += __shfl_xor_sync(0xffffffffu, p, 1);
            p += __shfl_xor_sync(0xffffffffu, p, 2);
            if (ng == 0) y[(size_t)(rowbase + t0 + tt) * DI + d] = p;
        }
    }
}

// ---------------- y = LN(y + D*x) * silu(z) -> fp16 ----------------
__global__ void k_ypost(const float* __restrict__ y, const float* __restrict__ xc,
                        const float* __restrict__ xz, const float* __restrict__ Dp,
                        const float* __restrict__ snw, const float* __restrict__ snb,
                        __half* __restrict__ ohi) {
    __shared__ float sh[8];
    int row = blockIdx.x;
    float v[6];
#pragma unroll
    for (int j = 0; j < 6; j++) {
        int c = threadIdx.x + j * 256;
        size_t idx = (size_t)row * DI + c;
        v[j] = y[idx] + Dp[c] * xc[idx];
    }
    float s = 0.f;
#pragma unroll
    for (int j = 0; j < 6; j++) s += v[j];
    float mean = blk_sum(s, sh) * (1.0f / DI);
    float sq = 0.f;
#pragma unroll
    for (int j = 0; j < 6; j++) { v[j] -= mean; sq += v[j] * v[j]; }
    float var = blk_sum(sq, sh) * (1.0f / DI);
    float iv = rsqrtf(var + EPS_LN);
#pragma unroll
    for (int j = 0; j < 6; j++) {
        int c = threadIdx.x + j * 256;
        float nv = v[j] * iv * snw[c] + snb[c];
        float z = xz[(size_t)row * (2 * DI) + DI + c];
        float o = nv * (z / (1.0f + expf(-z)));
        ohi[(size_t)row * DI + c] = __float2half_rn(o);
    }
}

// ---------------- mean-pool partial sums ----------------
__global__ void k_pool(const float* __restrict__ hn, float* __restrict__ pool) {
    int b = blockIdx.x;
    int chunk = blockIdx.y;
#pragma unroll
    for (int j = 0; j < 3; j++) {
        int d = threadIdx.x + j * 256;
        float s = 0.f;
        int l0 = chunk * 112;
        for (int l = l0; l < l0 + 112; l++)
            s += hn[((size_t)(b * LSEQ + l)) * DM + d];
        atomicAdd(&pool[b * DM + d], s);
    }
}

// ---------------- head ----------------
__global__ void k_head(const float* __restrict__ pool, const float* __restrict__ hw,
                       const float* __restrict__ hb, float* __restrict__ out) {
    int cls = blockIdx.x;
    int b   = threadIdx.x >> 5;
    int lane = threadIdx.x & 31;
    float s = 0.f;
    for (int d = lane; d < DM; d += 32)
        s += pool[b * DM + d] * hw[(size_t)cls * DM + d];
    s = warp_sum(s);
    if (lane == 0)
        out[b * NC + cls] = s * (1.0f / (float)LSEQ) + hb[cls];
}

// ---------------- launch ----------------
extern "C" void kernel_launch(void* const* d_in, const int* in_sizes, int n_in,
                              void* d_out, int out_size) {
    const float* x      = (const float*)d_in[0];
    const float* pw     = (const float*)d_in[1];
    const float* pb     = (const float*)d_in[2];
    const float* ce     = (const float*)d_in[3];
    const float* nw     = (const float*)d_in[4];
    const float* nb     = (const float*)d_in[5];
    const float* ipw    = (const float*)d_in[6];
    const float* cw     = (const float*)d_in[7];
    const float* cb     = (const float*)d_in[8];
    const float* xpw    = (const float*)d_in[9];
    const float* dtw    = (const float*)d_in[10];
    const float* dtb    = (const float*)d_in[11];
    const float* alog   = (const float*)d_in[12];
    const float* Dp     = (const float*)d_in[13];
    const float* snw    = (const float*)d_in[14];
    const float* snb    = (const float*)d_in[15];
    const float* opw    = (const float*)d_in[16];
    const float* nfw    = (const float*)d_in[17];
    const float* nfb    = (const float*)d_in[18];
    const float* hw     = (const float*)d_in[19];
    const float* hb     = (const float*)d_in[20];
    float* out = (float*)d_out;

    float *res, *hid, *hn, *xz, *xc, *dbc, *dtbuf, *ybuf, *pool;
    __half *wh, *ah, *al, *ph, *dbch, *dbcl;
    cudaGetSymbolAddress((void**)&res,   g_res);
    cudaGetSymbolAddress((void**)&hid,   g_hid);
    cudaGetSymbolAddress((void**)&hn,    g_hn);
    cudaGetSymbolAddress((void**)&xz,    g_xz);
    cudaGetSymbolAddress((void**)&xc,    g_xc);
    cudaGetSymbolAddress((void**)&dbc,   g_dbc);
    cudaGetSymbolAddress((void**)&dtbuf, g_dt);
    cudaGetSymbolAddress((void**)&ybuf,  g_y);
    cudaGetSymbolAddress((void**)&pool,  g_pool);
    cudaGetSymbolAddress((void**)&wh,    g_wh);
    cudaGetSymbolAddress((void**)&ah,    g_ah);
    cudaGetSymbolAddress((void**)&al,    g_al);
    cudaGetSymbolAddress((void**)&ph,    g_ph);
    cudaGetSymbolAddress((void**)&dbch,  g_dbch);
    cudaGetSymbolAddress((void**)&dbcl,  g_dbcl);

    cudaFuncSetAttribute(k_gemm_fp16<128>, cudaFuncAttributeMaxDynamicSharedMemorySize, GEMM_SMEM);
    cudaFuncSetAttribute(k_gemm_fp16<256>, cudaFuncAttributeMaxDynamicSharedMemorySize, GEMM_SMEM);

    const int ew_di = (int)(((size_t)MROWS * DI + 255) / 256);
    const int MB = MROWS / 128;   // 98

    // launch 1: big ipw convert
    k_splitw<<<(int)(((size_t)12288 * 768 + 255) / 256), 256>>>(
        ipw, wh + OFF_IPW, (size_t)12288 * 768);
    // launch 2: all other weight converts
    k_splitw_rest<<<(REST_LEN + 255) / 256, 256>>>(pw, xpw, dtw, opw, wh);
    // launch 3: im2col
    k_im2col<<<MROWS, 256>>>(x, ph);
    // launch 4: patch gemm (NT=256, bias + channel-embed fused, mode 1)
    k_gemm_fp16<256><<<dim3(3, MB), 512, GEMM_SMEM>>>(ph, nullptr, 256,
        wh + OFF_PW, 256, hid, DM, DM, 256, 1, pb, ce, nullptr, nullptr, nullptr);

    for (int i = 0; i < DEPTH; i++) {
        // launch 5 (i=0): resid_ln; launch 6 (i=0): in_proj gemm  <- profiled by -s 5 -c 1
        k_resid_ln<<<MROWS, 256>>>(hid, res, nullptr, ah,
                                   nw + i * DM, nb + i * DM, i == 0 ? 1 : 0, 1);
        // in_proj: NT=256 single-product
        k_gemm_fp16<256><<<dim3(12, MB), 512, GEMM_SMEM>>>(ah, nullptr, DM,
            wh + OFF_IPW + (size_t)i * 3072 * 768, DM,
            xz, 3072, 3072, DM, 0, nullptr, nullptr, nullptr, nullptr, nullptr);
        k_conv_silu<<<ew_di, 256>>>(xz, cw + (size_t)i * DI * 4, cb + i * DI, xc, ah, al);
        // x_proj: NT=128, 2-product (feeds scan B/C + dt)
        k_gemm_fp16<128><<<dim3(1, MB), 512, GEMM_SMEM>>>(ah, al, DI,
            wh + OFF_XPW + (size_t)i * 128 * 1536, DI,
            dbc, 80, 80, DI, 2, nullptr, nullptr, dbch, dbcl, nullptr);
        // dt gemm: NT=128, 2-product, fused softplus+bias (mode 3)
        k_gemm_fp16<128><<<dim3(12, MB), 512, GEMM_SMEM>>>(dbch, dbcl, 64,
            wh + OFF_DTW + (size_t)i * 1536 * 64, 64,
            dtbuf, DI, DI, 64, 3, nullptr, nullptr, nullptr, nullptr, dtb + i * DI);
        k_scan<<<dim3(DI / SCH, BATCH), 256>>>(dtbuf, xc, dbc,
                                               alog + (size_t)i * DI * DS, ybuf);
        k_ypost<<<MROWS, 256>>>(ybuf, xc, xz, Dp + i * DI, snw + i * DI, snb + i * DI, ah);
        // out_proj: NT=256 single-product
        k_gemm_fp16<256><<<dim3(3, MB), 512, GEMM_SMEM>>>(ah, nullptr, DI,
            wh + OFF_OPW + (size_t)i * 768 * 1536, DI,
            hid, DM, DM, DI, 0, nullptr, nullptr, nullptr, nullptr, nullptr);
    }

    // final residual + LN + pool + head
    k_resid_ln<<<MROWS, 256>>>(hid, res, hn, nullptr, nfw, nfb, 0, 0);
    cudaMemsetAsync(pool, 0, BATCH * DM * sizeof(float));
    k_pool<<<dim3(BATCH, 14), 256>>>(hn, pool);
    k_head<<<NC, 256>>>(pool, hw, hb, out);
}